// round 15
// baseline (speedup 1.0000x reference)
#include <cuda_runtime.h>
#include <cuda_fp16.h>
#include <cuda_pipeline.h>
#include <cstdint>

// LUTBlock: out[b,o] = sum_{t=0..15} table[t, idx[b,t], o]
// idx[b,t] = sum_c ((x[b, aa[t,c]] - x[b, ab[t,c]]) > 0) << c
//
// R15: race-free ballot-one-ahead. Triple x-buffer (R12), barrier between
// wait_prior and ballot (fixes R14's visibility race), prefetch of next
// iter's wave-A table rows from the ballot REGISTER within warps 0-1 (no
// cross-warp smem read). One __syncthreads per iteration.

#define B_SZ    16384
#define IN_F    1024
#define OUT_F   1024
#define GRID_MAIN 1184          // 148 SMs x 8 CTAs: one wave

#define TABLE_ELEMS (16 * 256 * 1024)   // 4M elements

__device__ __half g_table_h[TABLE_ELEMS];   // 8 MB fp16 scratch

// ---------------------------------------------------------------------------
// Pre-pass: fp32 table -> fp16 scratch. Each thread: 8 elems.
// ---------------------------------------------------------------------------
__global__ __launch_bounds__(256)
void convert_table_kernel(const float4* __restrict__ table4)
{
    const int i = blockIdx.x * blockDim.x + threadIdx.x;   // 0 .. 512K-1
    const float4 v0 = __ldg(&table4[2 * i + 0]);
    const float4 v1 = __ldg(&table4[2 * i + 1]);
    half2 h[4];
    h[0] = __floats2half2_rn(v0.x, v0.y);
    h[1] = __floats2half2_rn(v0.z, v0.w);
    h[2] = __floats2half2_rn(v1.x, v1.y);
    h[3] = __floats2half2_rn(v1.z, v1.w);
    reinterpret_cast<uint4*>(g_table_h)[i] = *reinterpret_cast<const uint4*>(h);
}

// ---------------------------------------------------------------------------
// Depth-2 fp16 tree reduction of 8 rows into fp32 acc (rel_err ~3.8e-4).
// ---------------------------------------------------------------------------
__device__ __forceinline__ void reduce8(const uint2* __restrict__ v, float4& acc)
{
#define H2(u) (*reinterpret_cast<const half2*>(&(u)))
    half2 p0 = __hadd2(H2(v[0].x), H2(v[1].x));
    half2 p1 = __hadd2(H2(v[2].x), H2(v[3].x));
    half2 p2 = __hadd2(H2(v[4].x), H2(v[5].x));
    half2 p3 = __hadd2(H2(v[6].x), H2(v[7].x));
    half2 qx0 = __hadd2(p0, p1);
    half2 qx1 = __hadd2(p2, p3);
    half2 r0 = __hadd2(H2(v[0].y), H2(v[1].y));
    half2 r1 = __hadd2(H2(v[2].y), H2(v[3].y));
    half2 r2 = __hadd2(H2(v[4].y), H2(v[5].y));
    half2 r3 = __hadd2(H2(v[6].y), H2(v[7].y));
    half2 qy0 = __hadd2(r0, r1);
    half2 qy1 = __hadd2(r2, r3);
#undef H2
    const float2 fx0 = __half22float2(qx0);
    const float2 fx1 = __half22float2(qx1);
    const float2 fy0 = __half22float2(qy0);
    const float2 fy1 = __half22float2(qy1);
    acc.x += fx0.x + fx1.x;
    acc.y += fx0.y + fx1.y;
    acc.z += fy0.x + fy1.x;
    acc.w += fy0.y + fy1.y;
}

// ---------------------------------------------------------------------------
// Ballot for warps 0-3 (tid<128): returns warp's packed index word; lane 0
// stores it to dst. Warps 0-1 additionally L1-prefetch the 8 wave-A rows of
// the NEXT batch from the register word (2 lines/lane, no smem read).
// ---------------------------------------------------------------------------
__device__ __forceinline__ void ballot_store_prefetch(
    const float* __restrict__ xr, int ia, int ibx, int tid, int lane,
    unsigned* __restrict__ dst, bool do_prefetch)
{
    const float d = xr[ia] - xr[ibx];
    const unsigned m = __ballot_sync(0xFFFFFFFFu, d > 0.0f);
    if (lane == 0) dst[tid >> 5] = m;
    if (do_prefetch && tid < 64) {
        // warp w (0/1) covers t = 4w + (lane>>3); row index = byte (lane>>3) of m
        const int t = ((tid >> 5) << 2) + (lane >> 3);
        const unsigned r = (m >> ((lane & 24))) & 0xFFu;
        const char* p = reinterpret_cast<const char*>(g_table_h)
                      + (size_t)t * 524288u + r * 2048u
                      + (size_t)(lane & 7) * 256u;
        asm volatile("prefetch.global.L1 [%0];" :: "l"(p));
        asm volatile("prefetch.global.L1 [%0];" :: "l"(p + 128));
    }
}

// ---------------------------------------------------------------------------
// Persistent main: 256 threads, occ 8, one bar per iter.
// Iter i (batch b, cur = i%3, slot = i&1):
//   1. cp.async x[b+2G] -> s_x[(cur+2)%3]; commit (uncond commit)
//   2. wait_prior(1)                (x[b+G] copies done, this thread)
//   3. __syncthreads                (all copies visible; s_pk[slot] published)
//   4. ballot b+G from s_x[(cur+1)%3] -> s_pk[slot^1] + wave-A prefetch
//   5. gather b with s_pk[slot]; STG
// Hazards (all write/read pairs separated by a step-3 barrier):
//   s_x[β] written iter j-1 (as cur+2), balloted iter j (as cur+1): bar j.3.
//   s_x[β] balloted iter j, rewritten iter j+2: bars j+1.3, j+2.3.
//   s_pk[s] written iter j.4, read iter j+1.5: bar j+1.3.
//   s_pk[s] read iter j.5, rewritten iter j+2.4 (wait: j+1 writes s^1,
//     j+2 writes s): bar j+2.3 after the j.5 read.
// ---------------------------------------------------------------------------
__global__ __launch_bounds__(256, 8)
void lut_persistent_kernel(const float4* __restrict__ x4,
                           const int* __restrict__ aa,
                           const int* __restrict__ ab,
                           float4* __restrict__ out4)
{
    __shared__ float s_x[3][IN_F];
    __shared__ __align__(16) unsigned s_pk[2][4];

    const int tid  = threadIdx.x;
    const int lane = tid & 31;
    const int b0   = blockIdx.x;

    int ia = 0, ibx = 0;
    if (tid < 128) {
        ia  = __ldg(&aa[tid]);
        ibx = __ldg(&ab[tid]);
    }
    const char* tbase = reinterpret_cast<const char*>(g_table_h) + tid * 8;

    // Prologue: x[b0] -> buf0, x[b0+G] -> buf1 (both valid: b0 < G < B/2).
    __pipeline_memcpy_async(&reinterpret_cast<float4*>(s_x[0])[tid],
                            &x4[(size_t)b0 * (IN_F / 4) + tid], 16);
    __pipeline_commit();
    __pipeline_memcpy_async(&reinterpret_cast<float4*>(s_x[1])[tid],
                            &x4[(size_t)(b0 + GRID_MAIN) * (IN_F / 4) + tid], 16);
    __pipeline_commit();
    __pipeline_wait_prior(1);           // b0 copies done (this thread)
    __syncthreads();                    // all b0 copies visible
    if (tid < 128)                      // ballot b0 -> slot 0 (+ prefetch)
        ballot_store_prefetch(s_x[0], ia, ibx, tid, lane, s_pk[0], true);
    // (s_pk[0] published by the first in-loop barrier)

    int cur  = 0;
    int slot = 0;
    for (int b = b0; b < B_SZ; b += GRID_MAIN) {
        // 1. prefetch x for b+2G
        {
            const int b2 = b + 2 * GRID_MAIN;
            int w2 = cur + 2; if (w2 >= 3) w2 -= 3;
            if (b2 < B_SZ)
                __pipeline_memcpy_async(&reinterpret_cast<float4*>(s_x[w2])[tid],
                                        &x4[(size_t)b2 * (IN_F / 4) + tid], 16);
            __pipeline_commit();
        }
        // 2. x[b+G] copies done (this thread's groups)
        __pipeline_wait_prior(1);
        // 3. make them visible to all threads; publish s_pk[slot]
        __syncthreads();

        // 4. ballot for b+G into slot^1 (+ wave-A prefetch for next iter)
        if ((b + GRID_MAIN) < B_SZ && tid < 128) {
            int nxt = cur + 1; if (nxt >= 3) nxt -= 3;
            ballot_store_prefetch(s_x[nxt], ia, ibx, tid, lane,
                                  s_pk[slot ^ 1], true);
        }

        // 5. gather-sum for batch b (s_pk[slot] published at step 3)
        const uint4 pk = *reinterpret_cast<const uint4*>(s_pk[slot]);
        float4 acc = make_float4(0.f, 0.f, 0.f, 0.f);
        {   // wave A: t = 0..7 (L1-prefetched last iter)
            uint2 v[8];
#pragma unroll
            for (int t = 0; t < 8; t++) {
                const unsigned wd = (t < 4) ? pk.x : pk.y;
                const unsigned r = __byte_perm(wd, 0u, 0x4440 + (t & 3));
                v[t] = __ldg(reinterpret_cast<const uint2*>(
                                 tbase + (size_t)t * 524288u + r * 2048u));
            }
            reduce8(v, acc);
        }
        {   // wave B: t = 8..15
            uint2 v[8];
#pragma unroll
            for (int t = 0; t < 8; t++) {
                const unsigned wd = (t < 4) ? pk.z : pk.w;
                const unsigned r = __byte_perm(wd, 0u, 0x4440 + (t & 3));
                v[t] = __ldg(reinterpret_cast<const uint2*>(
                                 tbase + (size_t)(t + 8) * 524288u + r * 2048u));
            }
            reduce8(v, acc);
        }
        out4[(size_t)b * (OUT_F / 4) + tid] = acc;

        cur = (cur + 1 == 3) ? 0 : cur + 1;
        slot ^= 1;
    }
}

extern "C" void kernel_launch(void* const* d_in, const int* in_sizes, int n_in,
                              void* d_out, int out_size)
{
    const float4* x4     = (const float4*)d_in[0];  // (B, IN_F) fp32
    const float4* table4 = (const float4*)d_in[1];  // (T, R, OUT_F) fp32
    const int*    aa     = (const int*)   d_in[2];  // (T, C) int32
    const int*    ab     = (const int*)   d_in[3];  // (T, C) int32
    float4*       out4   = (float4*)      d_out;    // (B, OUT_F) fp32

    (void)in_sizes; (void)n_in; (void)out_size;

    convert_table_kernel<<<TABLE_ELEMS / 8 / 256, 256>>>(table4);
    lut_persistent_kernel<<<GRID_MAIN, 256>>>(x4, aa, ab, out4);
}

// round 16
// speedup vs baseline: 1.0631x; 1.0631x over previous
#include <cuda_runtime.h>
#include <cuda_fp16.h>
#include <cuda_pipeline.h>
#include <cstdint>

// LUTBlock: out[b,o] = sum_{t=0..15} table[t, idx[b,t], o]
// idx[b,t] = sum_c ((x[b, aa[t,c]] - x[b, ab[t,c]]) > 0) << c
//
// R16 = R12 (verified best: 45.6us total, rel_err 3.8e-4).
// Persistent CTAs (grid = 148*8 = one wave, grid-stride over batches);
// cp.async triple-buffered x prefetch; ballot-packed indices; fp16 table
// scratch; two front-batched 8x LDG.64 waves + depth-2 HADD2 tree.
// Falsified variants (do not re-try): L1 prefetch of table rows (R14/R15,
// +L2 traffic), kernel fusion via grid barrier (R13, serializes), LDG.32
// (R11), occ-6 wide MLP (R9), 2-batch CTAs (R4).

#define B_SZ    16384
#define IN_F    1024
#define OUT_F   1024
#define T_CNT   16
#define GRID_MAIN 1184          // 148 SMs x 8 CTAs: exactly one wave

#define TABLE_ELEMS (16 * 256 * 1024)   // 4M elements

// 8 MB fp16 scratch copy of the table (device global: allocation-free).
__device__ __half g_table_h[TABLE_ELEMS];

// ---------------------------------------------------------------------------
// Pre-pass: fp32 table -> fp16 scratch. Each thread: 8 elems (32B in, 16B out).
// ---------------------------------------------------------------------------
__global__ __launch_bounds__(256)
void convert_table_kernel(const float4* __restrict__ table4)
{
    const int i = blockIdx.x * blockDim.x + threadIdx.x;   // 0 .. 512K-1
    const float4 v0 = __ldg(&table4[2 * i + 0]);
    const float4 v1 = __ldg(&table4[2 * i + 1]);
    half2 h[4];
    h[0] = __floats2half2_rn(v0.x, v0.y);
    h[1] = __floats2half2_rn(v0.z, v0.w);
    h[2] = __floats2half2_rn(v1.x, v1.y);
    h[3] = __floats2half2_rn(v1.z, v1.w);
    reinterpret_cast<uint4*>(g_table_h)[i] = *reinterpret_cast<const uint4*>(h);
}

// ---------------------------------------------------------------------------
// Reduce 8 table values (uint2 of 4 halves) with a depth-2 fp16 tree,
// accumulating the two quad partials into fp32 acc. (rel_err ~3.8e-4)
// ---------------------------------------------------------------------------
__device__ __forceinline__ void reduce8(const uint2* __restrict__ v, float4& acc)
{
#define H2(u) (*reinterpret_cast<const half2*>(&(u)))
    half2 p0 = __hadd2(H2(v[0].x), H2(v[1].x));
    half2 p1 = __hadd2(H2(v[2].x), H2(v[3].x));
    half2 p2 = __hadd2(H2(v[4].x), H2(v[5].x));
    half2 p3 = __hadd2(H2(v[6].x), H2(v[7].x));
    half2 qx0 = __hadd2(p0, p1);
    half2 qx1 = __hadd2(p2, p3);
    half2 r0 = __hadd2(H2(v[0].y), H2(v[1].y));
    half2 r1 = __hadd2(H2(v[2].y), H2(v[3].y));
    half2 r2 = __hadd2(H2(v[4].y), H2(v[5].y));
    half2 r3 = __hadd2(H2(v[6].y), H2(v[7].y));
    half2 qy0 = __hadd2(r0, r1);
    half2 qy1 = __hadd2(r2, r3);
#undef H2
    const float2 fx0 = __half22float2(qx0);
    const float2 fx1 = __half22float2(qx1);
    const float2 fy0 = __half22float2(qy0);
    const float2 fy1 = __half22float2(qy1);
    acc.x += fx0.x + fx1.x;
    acc.y += fx0.y + fx1.y;
    acc.z += fy0.x + fy1.x;
    acc.w += fy0.y + fy1.y;
}

// ---------------------------------------------------------------------------
// Persistent main kernel: 256 threads, occ 8. Grid-stride over batches with a
// depth-2 cp.async x-prefetch pipeline and one __syncthreads per batch.
//
// Per-iter schedule (buffers: s_x triple, s_pk double):
//   1. cp.async x[b+2*GRID] -> s_x[(p+2)%3]; commit
//   2. warps 0-3: ballot on s_x[p%3] -> s_pk[p&1]   (one STS.32/warp)
//   3. wait_prior(1)  (x[b+GRID]'s group complete), __syncthreads
//   4. gather from fp16 table using s_pk[p&1], STG out[b]
// All cross-thread smem reads follow a barrier after the producing writes.
// ---------------------------------------------------------------------------
__global__ __launch_bounds__(256, 8)
void lut_persistent_kernel(const float4* __restrict__ x4,
                           const int* __restrict__ aa,
                           const int* __restrict__ ab,
                           float4* __restrict__ out4)
{
    __shared__ float s_x[3][IN_F];
    __shared__ __align__(16) unsigned s_pk[2][4];

    const int tid  = threadIdx.x;
    const int lane = tid & 31;

    // Loop-invariant anchors for the ballot warps.
    int ia = 0, ibx = 0;
    if (tid < 128) {
        ia  = __ldg(&aa[tid]);
        ibx = __ldg(&ab[tid]);
    }

    const char* tbase = reinterpret_cast<const char*>(g_table_h) + tid * 8;

    // Prologue: prefetch batches b0 and b0+GRID.
    const int b0 = blockIdx.x;
    __pipeline_memcpy_async(&reinterpret_cast<float4*>(s_x[0])[tid],
                            &x4[(size_t)b0 * (IN_F / 4) + tid], 16);
    __pipeline_commit();
    {
        const int b1 = b0 + GRID_MAIN;
        if (b1 < B_SZ)
            __pipeline_memcpy_async(&reinterpret_cast<float4*>(s_x[1])[tid],
                                    &x4[(size_t)b1 * (IN_F / 4) + tid], 16);
        __pipeline_commit();
    }
    __pipeline_wait_prior(1);   // b0's tile copies complete (this thread)
    __syncthreads();            // all threads' b0 copies visible

    int cur = 0;                // s_x buffer of current batch
    int par = 0;                // s_pk parity
    for (int b = b0; b < B_SZ; b += GRID_MAIN) {
        // 1. prefetch batch b + 2*GRID (depth-2 pipeline; empty group if OOB)
        {
            const int b2 = b + 2 * GRID_MAIN;
            int nxt2 = cur + 2; if (nxt2 >= 3) nxt2 -= 3;
            if (b2 < B_SZ)
                __pipeline_memcpy_async(&reinterpret_cast<float4*>(s_x[nxt2])[tid],
                                        &x4[(size_t)b2 * (IN_F / 4) + tid], 16);
            __pipeline_commit();
        }

        // 2. ballot: warp w's word = packed index bytes for t = 4w..4w+3
        if (tid < 128) {
            const float* xr = s_x[cur];
            const float d = xr[ia] - xr[ibx];
            const unsigned m = __ballot_sync(0xFFFFFFFFu, d > 0.0f);
            if (lane == 0) s_pk[par][tid >> 5] = m;
        }

        // 3. ensure next batch's x tile has landed; publish indices
        __pipeline_wait_prior(1);
        __syncthreads();

        // 4. gather-sum from fp16 table (L2-resident), two 8-load waves
        const uint4 pk = *reinterpret_cast<const uint4*>(s_pk[par]);
        float4 acc = make_float4(0.f, 0.f, 0.f, 0.f);
        {   // wave A: t = 0..7
            uint2 v[8];
#pragma unroll
            for (int t = 0; t < 8; t++) {
                const unsigned wd = (t < 4) ? pk.x : pk.y;
                const unsigned r = __byte_perm(wd, 0u, 0x4440 + (t & 3));
                v[t] = __ldg(reinterpret_cast<const uint2*>(
                                 tbase + (size_t)t * 524288u + r * 2048u));
            }
            reduce8(v, acc);
        }
        {   // wave B: t = 8..15
            uint2 v[8];
#pragma unroll
            for (int t = 0; t < 8; t++) {
                const unsigned wd = (t < 4) ? pk.z : pk.w;
                const unsigned r = __byte_perm(wd, 0u, 0x4440 + (t & 3));
                v[t] = __ldg(reinterpret_cast<const uint2*>(
                                 tbase + (size_t)(t + 8) * 524288u + r * 2048u));
            }
            reduce8(v, acc);
        }
        out4[(size_t)b * (OUT_F / 4) + tid] = acc;

        // advance pipeline state
        cur = (cur + 1 == 3) ? 0 : cur + 1;
        par ^= 1;
    }
}

extern "C" void kernel_launch(void* const* d_in, const int* in_sizes, int n_in,
                              void* d_out, int out_size)
{
    const float4* x4     = (const float4*)d_in[0];  // (B, IN_F) fp32
    const float4* table4 = (const float4*)d_in[1];  // (T, R, OUT_F) fp32
    const int*    aa     = (const int*)   d_in[2];  // (T, C) int32
    const int*    ab     = (const int*)   d_in[3];  // (T, C) int32
    float4*       out4   = (float4*)      d_out;    // (B, OUT_F) fp32

    (void)in_sizes; (void)n_in; (void)out_size;

    // Pre-pass: table -> fp16 scratch (8 elems per thread)
    convert_table_kernel<<<TABLE_ELEMS / 8 / 256, 256>>>(table4);

    // Persistent main: one wave of CTAs, grid-stride over batches
    lut_persistent_kernel<<<GRID_MAIN, 256>>>(x4, aa, ab, out4);
}

// round 17
// speedup vs baseline: 1.0831x; 1.0189x over previous
#include <cuda_runtime.h>
#include <cuda_fp16.h>
#include <cuda_pipeline.h>
#include <cstdint>

// LUTBlock: out[b,o] = sum_{t=0..15} table[t, idx[b,t], o]
// idx[b,t] = sum_c ((x[b, aa[t,c]] - x[b, ab[t,c]]) > 0) << c
//
// R17 = R16 + (a) GRID 1216: GB300 has 152 SMs (B300_MICROARCH GB300 delta),
// so one full wave at occ 8 is 152*8, rebalancing per-SM batch counts;
// (b) __stcs streaming output stores (out is write-once, keep the 8MB fp16
// table L2-resident instead).
// Falsified (do not re-try): L1 table prefetch (R14/15), grid-barrier fusion
// (R13), LDG.32 (R11), occ-6 MLP (R9), 2-batch CTAs (R4), bf16/int8 table.

#define B_SZ    16384
#define IN_F    1024
#define OUT_F   1024
#define GRID_MAIN 1216          // 152 SMs x 8 CTAs: exactly one wave on GB300

#define TABLE_ELEMS (16 * 256 * 1024)   // 4M elements

// 8 MB fp16 scratch copy of the table (device global: allocation-free).
__device__ __half g_table_h[TABLE_ELEMS];

// ---------------------------------------------------------------------------
// Pre-pass: fp32 table -> fp16 scratch. Each thread: 8 elems (32B in, 16B out).
// ---------------------------------------------------------------------------
__global__ __launch_bounds__(256)
void convert_table_kernel(const float4* __restrict__ table4)
{
    const int i = blockIdx.x * blockDim.x + threadIdx.x;   // 0 .. 512K-1
    const float4 v0 = __ldg(&table4[2 * i + 0]);
    const float4 v1 = __ldg(&table4[2 * i + 1]);
    half2 h[4];
    h[0] = __floats2half2_rn(v0.x, v0.y);
    h[1] = __floats2half2_rn(v0.z, v0.w);
    h[2] = __floats2half2_rn(v1.x, v1.y);
    h[3] = __floats2half2_rn(v1.z, v1.w);
    reinterpret_cast<uint4*>(g_table_h)[i] = *reinterpret_cast<const uint4*>(h);
}

// ---------------------------------------------------------------------------
// Reduce 8 table values (uint2 of 4 halves) with a depth-2 fp16 tree,
// accumulating the two quad partials into fp32 acc. (rel_err ~3.8e-4)
// ---------------------------------------------------------------------------
__device__ __forceinline__ void reduce8(const uint2* __restrict__ v, float4& acc)
{
#define H2(u) (*reinterpret_cast<const half2*>(&(u)))
    half2 p0 = __hadd2(H2(v[0].x), H2(v[1].x));
    half2 p1 = __hadd2(H2(v[2].x), H2(v[3].x));
    half2 p2 = __hadd2(H2(v[4].x), H2(v[5].x));
    half2 p3 = __hadd2(H2(v[6].x), H2(v[7].x));
    half2 qx0 = __hadd2(p0, p1);
    half2 qx1 = __hadd2(p2, p3);
    half2 r0 = __hadd2(H2(v[0].y), H2(v[1].y));
    half2 r1 = __hadd2(H2(v[2].y), H2(v[3].y));
    half2 r2 = __hadd2(H2(v[4].y), H2(v[5].y));
    half2 r3 = __hadd2(H2(v[6].y), H2(v[7].y));
    half2 qy0 = __hadd2(r0, r1);
    half2 qy1 = __hadd2(r2, r3);
#undef H2
    const float2 fx0 = __half22float2(qx0);
    const float2 fx1 = __half22float2(qx1);
    const float2 fy0 = __half22float2(qy0);
    const float2 fy1 = __half22float2(qy1);
    acc.x += fx0.x + fx1.x;
    acc.y += fx0.y + fx1.y;
    acc.z += fy0.x + fy1.x;
    acc.w += fy0.y + fy1.y;
}

// ---------------------------------------------------------------------------
// Persistent main kernel: 256 threads, occ 8, one wave of 1216 CTAs.
// Per-iter schedule (s_x triple-buffered, s_pk double):
//   1. cp.async x[b+2*GRID] -> s_x[(p+2)%3]; commit
//   2. warps 0-3: ballot on s_x[p%3] -> s_pk[p&1]   (one STS.32/warp)
//   3. wait_prior(1), __syncthreads   (x[b+GRID] visible; s_pk published)
//   4. gather from fp16 table using s_pk[p&1]; streaming STG out[b]
// ---------------------------------------------------------------------------
__global__ __launch_bounds__(256, 8)
void lut_persistent_kernel(const float4* __restrict__ x4,
                           const int* __restrict__ aa,
                           const int* __restrict__ ab,
                           float4* __restrict__ out4)
{
    __shared__ float s_x[3][IN_F];
    __shared__ __align__(16) unsigned s_pk[2][4];

    const int tid  = threadIdx.x;
    const int lane = tid & 31;

    // Loop-invariant anchors for the ballot warps.
    int ia = 0, ibx = 0;
    if (tid < 128) {
        ia  = __ldg(&aa[tid]);
        ibx = __ldg(&ab[tid]);
    }

    const char* tbase = reinterpret_cast<const char*>(g_table_h) + tid * 8;

    // Prologue: prefetch batches b0 and b0+GRID.
    const int b0 = blockIdx.x;
    __pipeline_memcpy_async(&reinterpret_cast<float4*>(s_x[0])[tid],
                            &x4[(size_t)b0 * (IN_F / 4) + tid], 16);
    __pipeline_commit();
    {
        const int b1 = b0 + GRID_MAIN;
        if (b1 < B_SZ)
            __pipeline_memcpy_async(&reinterpret_cast<float4*>(s_x[1])[tid],
                                    &x4[(size_t)b1 * (IN_F / 4) + tid], 16);
        __pipeline_commit();
    }
    __pipeline_wait_prior(1);   // b0's tile copies complete (this thread)
    __syncthreads();            // all threads' b0 copies visible

    int cur = 0;                // s_x buffer of current batch
    int par = 0;                // s_pk parity
    for (int b = b0; b < B_SZ; b += GRID_MAIN) {
        // 1. prefetch batch b + 2*GRID (depth-2 pipeline; empty group if OOB)
        {
            const int b2 = b + 2 * GRID_MAIN;
            int nxt2 = cur + 2; if (nxt2 >= 3) nxt2 -= 3;
            if (b2 < B_SZ)
                __pipeline_memcpy_async(&reinterpret_cast<float4*>(s_x[nxt2])[tid],
                                        &x4[(size_t)b2 * (IN_F / 4) + tid], 16);
            __pipeline_commit();
        }

        // 2. ballot: warp w's word = packed index bytes for t = 4w..4w+3
        if (tid < 128) {
            const float* xr = s_x[cur];
            const float d = xr[ia] - xr[ibx];
            const unsigned m = __ballot_sync(0xFFFFFFFFu, d > 0.0f);
            if (lane == 0) s_pk[par][tid >> 5] = m;
        }

        // 3. ensure next batch's x tile has landed; publish indices
        __pipeline_wait_prior(1);
        __syncthreads();

        // 4. gather-sum from fp16 table (L2-resident), two 8-load waves
        const uint4 pk = *reinterpret_cast<const uint4*>(s_pk[par]);
        float4 acc = make_float4(0.f, 0.f, 0.f, 0.f);
        {   // wave A: t = 0..7
            uint2 v[8];
#pragma unroll
            for (int t = 0; t < 8; t++) {
                const unsigned wd = (t < 4) ? pk.x : pk.y;
                const unsigned r = __byte_perm(wd, 0u, 0x4440 + (t & 3));
                v[t] = __ldg(reinterpret_cast<const uint2*>(
                                 tbase + (size_t)t * 524288u + r * 2048u));
            }
            reduce8(v, acc);
        }
        {   // wave B: t = 8..15
            uint2 v[8];
#pragma unroll
            for (int t = 0; t < 8; t++) {
                const unsigned wd = (t < 4) ? pk.z : pk.w;
                const unsigned r = __byte_perm(wd, 0u, 0x4440 + (t & 3));
                v[t] = __ldg(reinterpret_cast<const uint2*>(
                                 tbase + (size_t)(t + 8) * 524288u + r * 2048u));
            }
            reduce8(v, acc);
        }
        // Streaming store: out is write-once; keep the table in L2.
        __stcs(&out4[(size_t)b * (OUT_F / 4) + tid], acc);

        // advance pipeline state
        cur = (cur + 1 == 3) ? 0 : cur + 1;
        par ^= 1;
    }
}

extern "C" void kernel_launch(void* const* d_in, const int* in_sizes, int n_in,
                              void* d_out, int out_size)
{
    const float4* x4     = (const float4*)d_in[0];  // (B, IN_F) fp32
    const float4* table4 = (const float4*)d_in[1];  // (T, R, OUT_F) fp32
    const int*    aa     = (const int*)   d_in[2];  // (T, C) int32
    const int*    ab     = (const int*)   d_in[3];  // (T, C) int32
    float4*       out4   = (float4*)      d_out;    // (B, OUT_F) fp32

    (void)in_sizes; (void)n_in; (void)out_size;

    // Pre-pass: table -> fp16 scratch (8 elems per thread)
    convert_table_kernel<<<TABLE_ELEMS / 8 / 256, 256>>>(table4);

    // Persistent main: one wave of CTAs (152 SMs x 8), grid-stride batches
    lut_persistent_kernel<<<GRID_MAIN, 256>>>(x4, aa, ab, out4);
}